// round 8
// baseline (speedup 1.0000x reference)
#include <cuda_runtime.h>
#include <cstdint>

#define BB   2
#define SS   2048
#define HIDD 1024
#define NHH  4
#define HDD  256

// Scratch (allocation-free rule -> __device__ globals)
__device__ float g_q[BB*NHH*SS*HDD];
__device__ float g_k[BB*NHH*SS*HDD];
__device__ float g_v[BB*NHH*SS*HDD];
__device__ float g_o[BB*SS*HIDD];

// ---------------------------------------------------------------------------
// helpers (base PTX ISA, works on sm_103 target)
// ---------------------------------------------------------------------------
__device__ __forceinline__ void mma168(float* c, const uint32_t* a, const uint32_t* b) {
    asm volatile(
        "mma.sync.aligned.m16n8k8.row.col.f32.tf32.tf32.f32 "
        "{%0,%1,%2,%3}, {%4,%5,%6,%7}, {%8,%9}, {%0,%1,%2,%3};"
        : "+f"(c[0]), "+f"(c[1]), "+f"(c[2]), "+f"(c[3])
        : "r"(a[0]), "r"(a[1]), "r"(a[2]), "r"(a[3]), "r"(b[0]), "r"(b[1]));
}
__device__ __forceinline__ uint32_t f2tf32(float x) {
    uint32_t u;
    asm("cvt.rna.tf32.f32 %0, %1;" : "=r"(u) : "f"(x));
    return u;
}
__device__ __forceinline__ uint32_t smem_u32(const void* p) {
    uint32_t a;
    asm("{ .reg .u64 t; cvta.to.shared.u64 t, %1; cvt.u32.u64 %0, t; }"
        : "=r"(a) : "l"(p));
    return a;
}
__device__ __forceinline__ void cp_async16(uint32_t saddr, const void* gptr) {
    asm volatile("cp.async.cg.shared.global [%0], [%1], 16;"
                 :: "r"(saddr), "l"(gptr) : "memory");
}
#define CP_COMMIT() asm volatile("cp.async.commit_group;" ::: "memory")
#define CP_WAIT(n)  asm volatile("cp.async.wait_group %0;" :: "n"(n) : "memory")

// ===========================================================================
// GEMM kernels: tf32 mma.sync with single-stage register prefetch.
// ===========================================================================
#define TSTR 36

__device__ __forceinline__ void mma_mainloop(
    const float* __restrict__ A, const float* __restrict__ Bmat,
    int m0, int n0, uint32_t* As, uint32_t* Bs, float c[4][4][4])
{
    const int tid  = threadIdx.x;
    const int wid  = tid >> 5, lane = tid & 31;
    const int g    = lane >> 2, tg = lane & 3;
    const int warpM = wid >> 2, warpN = wid & 3;

    const int lrow = tid >> 1;            // 0..127
    const int lcw  = (tid & 1) * 16;      // 0 or 16

#pragma unroll
    for (int mt = 0; mt < 4; mt++)
#pragma unroll
        for (int nt = 0; nt < 4; nt++)
#pragma unroll
            for (int r = 0; r < 4; r++) c[mt][nt][r] = 0.f;

    const float* Agr = A    + (size_t)(m0 + lrow) * 1024 + lcw;
    const float* Bgr = Bmat + (size_t)(n0 + lrow) * 1024 + lcw;

    float4 pa[4], pb[4];
#pragma unroll
    for (int j = 0; j < 4; j++) {
        pa[j] = *(const float4*)(Agr + 4 * j);
        pb[j] = *(const float4*)(Bgr + 4 * j);
    }

    for (int kt = 0; kt < 32; kt++) {
        __syncthreads();                  // prev mma done reading smem
#pragma unroll
        for (int j = 0; j < 4; j++) {
            *(uint4*)&As[lrow * TSTR + lcw + 4 * j] =
                make_uint4(f2tf32(pa[j].x), f2tf32(pa[j].y), f2tf32(pa[j].z), f2tf32(pa[j].w));
            *(uint4*)&Bs[lrow * TSTR + lcw + 4 * j] =
                make_uint4(f2tf32(pb[j].x), f2tf32(pb[j].y), f2tf32(pb[j].z), f2tf32(pb[j].w));
        }
        __syncthreads();

        if (kt < 31) {                    // prefetch next k-slice (overlaps mma)
            const float* An = Agr + (kt + 1) * 32;
            const float* Bn = Bgr + (kt + 1) * 32;
#pragma unroll
            for (int j = 0; j < 4; j++) {
                pa[j] = *(const float4*)(An + 4 * j);
                pb[j] = *(const float4*)(Bn + 4 * j);
            }
        }

#pragma unroll
        for (int ks = 0; ks < 4; ks++) {
            const int kk = ks * 8;
            uint32_t a[4][4], b[4][2];
#pragma unroll
            for (int mt = 0; mt < 4; mt++) {
                int r = warpM * 64 + mt * 16 + g;
                a[mt][0] = As[r * TSTR + kk + tg];
                a[mt][1] = As[(r + 8) * TSTR + kk + tg];
                a[mt][2] = As[r * TSTR + kk + tg + 4];
                a[mt][3] = As[(r + 8) * TSTR + kk + tg + 4];
            }
#pragma unroll
            for (int nt = 0; nt < 4; nt++) {
                int n = warpN * 32 + nt * 8 + g;
                b[nt][0] = Bs[n * TSTR + kk + tg];
                b[nt][1] = Bs[n * TSTR + kk + tg + 4];
            }
#pragma unroll
            for (int mt = 0; mt < 4; mt++)
#pragma unroll
                for (int nt = 0; nt < 4; nt++)
                    mma168(c[mt][nt], a[mt], b[nt]);
        }
    }
}

__global__ __launch_bounds__(256, 1) void qkv_mma_kernel(
    const float* __restrict__ A, const float* __restrict__ W,
    const float* __restrict__ fr, const float* __restrict__ fi)
{
    __shared__ uint32_t As[128 * TSTR];
    __shared__ uint32_t Bs[128 * TSTR];
    const int tid  = threadIdx.x;
    const int wid  = tid >> 5, lane = tid & 31;
    const int g    = lane >> 2, tg = lane & 3;
    const int warpM = wid >> 2, warpN = wid & 3;
    const int m0 = blockIdx.y * 128;
    const int n0 = blockIdx.x * 128;

    float c[4][4][4];
    mma_mainloop(A, W, m0, n0, As, Bs, c);

    const int which = n0 >> 10;
#pragma unroll
    for (int mt = 0; mt < 4; mt++) {
#pragma unroll
        for (int half = 0; half < 2; half++) {
            int m  = m0 + warpM * 64 + mt * 16 + g + half * 8;
            int bb = m >> 11;
            int ss = m & 2047;
#pragma unroll
            for (int nt = 0; nt < 4; nt++) {
                int n = n0 + warpN * 32 + nt * 8 + tg * 2;
                int h = (n >> 8) & 3;
                int d = n & 255;
                float x0 = c[mt][nt][half * 2];
                float x1 = c[mt][nt][half * 2 + 1];
                size_t oidx = (((size_t)(bb * NHH + h)) * SS + ss) * HDD + d;
                if (which == 2) {
                    *(float2*)&g_v[oidx] = make_float2(x0, x1);
                } else {
                    float fre = __ldg(&fr[(size_t)ss * 128 + (d >> 1)]);
                    float fim = __ldg(&fi[(size_t)ss * 128 + (d >> 1)]);
                    float o0 = x0 * fre - x1 * fim;
                    float o1 = x0 * fim + x1 * fre;
                    float* dst = (which == 0) ? g_q : g_k;
                    *(float2*)&dst[oidx] = make_float2(o0, o1);
                }
            }
        }
    }
}

__global__ __launch_bounds__(256, 1) void o_mma_kernel(
    const float* __restrict__ A, const float* __restrict__ W,
    float* __restrict__ C)
{
    __shared__ uint32_t As[128 * TSTR];
    __shared__ uint32_t Bs[128 * TSTR];
    const int tid  = threadIdx.x;
    const int wid  = tid >> 5, lane = tid & 31;
    const int g    = lane >> 2, tg = lane & 3;
    const int warpM = wid >> 2, warpN = wid & 3;
    const int m0 = blockIdx.y * 128;
    const int n0 = blockIdx.x * 128;

    float c[4][4][4];
    mma_mainloop(A, W, m0, n0, As, Bs, c);

#pragma unroll
    for (int mt = 0; mt < 4; mt++) {
#pragma unroll
        for (int half = 0; half < 2; half++) {
            int m = m0 + warpM * 64 + mt * 16 + g + half * 8;
#pragma unroll
            for (int nt = 0; nt < 4; nt++) {
                int n = n0 + warpN * 32 + nt * 8 + tg * 2;
                *(float2*)&C[(size_t)m * 1024 + n] =
                    make_float2(c[mt][nt][half * 2], c[mt][nt][half * 2 + 1]);
            }
        }
    }
}

// ===========================================================================
// Kernel 2: tensor-core causal flash attention (tf32 mma.sync + cp.async).
// K/V tiles fetched with cp.async (raw fp32; tf32 mma truncates mantissa).
// Two commit groups: K waited before S; V waited only after softmax so the
// V fill overlaps S + softmax.
// Each thread copies one FULL 64-float chunk: row tid>>2, cols (tid&3)*64..+63.
// ===========================================================================
#define QSTR 260
#define VSTR 260
#define PSTR 68

extern __shared__ uint32_t attn_sm[];

__global__ __launch_bounds__(256, 1) void attn_mma_kernel(
    const float* __restrict__ qg, const float* __restrict__ kg,
    const float* __restrict__ vg, float* __restrict__ og)
{
    uint32_t* Qs = attn_sm;                 // [64][QSTR] tf32 (rounded)
    uint32_t* Ks = Qs + 64 * QSTR;          // [64][QSTR] raw fp32
    uint32_t* Vs = Ks + 64 * QSTR;          // [64][VSTR] raw fp32
    uint32_t* Ps = Vs + 64 * VSTR;          // [64][PSTR] tf32
    float* mS   = (float*)(Ps + 64 * PSTR); // [64]
    float* lS   = mS + 64;                  // [64]
    float* pmax = lS + 64;                  // [2][64]
    float* psum = pmax + 128;               // [2][64]

    const int tid  = threadIdx.x;
    const int wid  = tid >> 5, lane = tid & 31;
    const int g    = lane >> 2, tg = lane & 3;
    const int warpRow = wid >> 1;
    const int warpCol = wid & 1;

    const int qt  = gridDim.x - 1 - blockIdx.x;   // heavy CTAs first
    const int q0  = qt * 64;
    const int h   = blockIdx.y;
    const int b   = blockIdx.z;
    const size_t base = ((size_t)(b * NHH + h)) * SS * HDD;
    const float scale = 0.0625f;

    // per-thread slice for tile copies: row = tid>>2, 64 floats at (tid&3)*64
    const int crow = tid >> 2;
    const int cc0  = (tid & 3) * 64;
    const uint32_t ks_base = smem_u32(Ks);
    const uint32_t vs_base = smem_u32(Vs);

    // load Q tile (scaled, rounded tf32)
#pragma unroll
    for (int it = 0; it < 16; it++) {
        int f   = tid + it * 256;
        int row = f >> 6;
        int c4  = (f & 63) * 4;
        float4 v = *(const float4*)&qg[base + (size_t)(q0 + row) * HDD + c4];
        *(uint4*)&Qs[row * QSTR + c4] =
            make_uint4(f2tf32(v.x * scale), f2tf32(v.y * scale),
                       f2tf32(v.z * scale), f2tf32(v.w * scale));
    }
    if (tid < 64) { mS[tid] = -1e30f; lS[tid] = 0.f; }

    float o[16][4];
#pragma unroll
    for (int nt = 0; nt < 16; nt++)
#pragma unroll
        for (int r = 0; r < 4; r++) o[nt][r] = 0.f;

    const int rg = warpRow * 16 + g;

    const int nkb = qt + 1;
    for (int kbi = 0; kbi < nkb; kbi++) {
        const int k0 = kbi * 64;
        __syncthreads();                    // prev iter done reading Ks/Vs/Ps

        // async K tile, then V tile (separate groups); FULL 64x256 each
        {
            const float* kgr = kg + base + (size_t)(k0 + crow) * HDD + cc0;
            uint32_t kdst = ks_base + (uint32_t)(crow * QSTR + cc0) * 4u;
#pragma unroll
            for (int j = 0; j < 16; j++)
                cp_async16(kdst + 16u * j, kgr + 4 * j);
            CP_COMMIT();
            const float* vgr = vg + base + (size_t)(k0 + crow) * HDD + cc0;
            uint32_t vdst = vs_base + (uint32_t)(crow * VSTR + cc0) * 4u;
#pragma unroll
            for (int j = 0; j < 16; j++)
                cp_async16(vdst + 16u * j, vgr + 4 * j);
            CP_COMMIT();
        }
        CP_WAIT(1);                         // K arrived (V may still be in flight)
        __syncthreads();

        // ---- S = Q K^T : warp tile 16 x 32 ----
        float s[4][4];
#pragma unroll
        for (int nt = 0; nt < 4; nt++)
#pragma unroll
            for (int r = 0; r < 4; r++) s[nt][r] = 0.f;

#pragma unroll 4
        for (int kk = 0; kk < 256; kk += 8) {
            uint32_t a[4];
            a[0] = Qs[rg * QSTR + kk + tg];
            a[1] = Qs[(rg + 8) * QSTR + kk + tg];
            a[2] = Qs[rg * QSTR + kk + tg + 4];
            a[3] = Qs[(rg + 8) * QSTR + kk + tg + 4];
#pragma unroll
            for (int nt = 0; nt < 4; nt++) {
                int n = warpCol * 32 + nt * 8 + g;
                uint32_t bb2[2];
                bb2[0] = Ks[n * QSTR + kk + tg];
                bb2[1] = Ks[n * QSTR + kk + tg + 4];
                mma168(s[nt], a, bb2);
            }
        }

        // causal mask on diagonal tile
        if (kbi == qt) {
#pragma unroll
            for (int nt = 0; nt < 4; nt++) {
#pragma unroll
                for (int r = 0; r < 4; r++) {
                    int row = q0 + rg + ((r & 2) ? 8 : 0);
                    int col = k0 + warpCol * 32 + nt * 8 + 2 * tg + (r & 1);
                    if (col > row) s[nt][r] = -1e30f;
                }
            }
        }

        // partial row max within this warp's 32 cols
        float mx0 = -1e30f, mx1 = -1e30f;
#pragma unroll
        for (int nt = 0; nt < 4; nt++) {
            mx0 = fmaxf(mx0, fmaxf(s[nt][0], s[nt][1]));
            mx1 = fmaxf(mx1, fmaxf(s[nt][2], s[nt][3]));
        }
        mx0 = fmaxf(mx0, __shfl_xor_sync(0xffffffffu, mx0, 1));
        mx0 = fmaxf(mx0, __shfl_xor_sync(0xffffffffu, mx0, 2));
        mx1 = fmaxf(mx1, __shfl_xor_sync(0xffffffffu, mx1, 1));
        mx1 = fmaxf(mx1, __shfl_xor_sync(0xffffffffu, mx1, 2));
        if (tg == 0) {
            pmax[warpCol * 64 + rg]     = mx0;
            pmax[warpCol * 64 + rg + 8] = mx1;
        }
        __syncthreads();

        float m0old = mS[rg], m1old = mS[rg + 8];
        float m0 = fmaxf(m0old, fmaxf(pmax[rg],     pmax[64 + rg]));
        float m1 = fmaxf(m1old, fmaxf(pmax[rg + 8], pmax[64 + rg + 8]));
        float resc0 = __expf(m0old - m0);
        float resc1 = __expf(m1old - m1);

        float sum0 = 0.f, sum1 = 0.f;
#pragma unroll
        for (int nt = 0; nt < 4; nt++) {
            int cl = warpCol * 32 + nt * 8 + 2 * tg;
            float p0 = __expf(s[nt][0] - m0);
            float p1 = __expf(s[nt][1] - m0);
            float p2 = __expf(s[nt][2] - m1);
            float p3 = __expf(s[nt][3] - m1);
            sum0 += p0 + p1;
            sum1 += p2 + p3;
            Ps[rg * PSTR + cl]           = f2tf32(p0);
            Ps[rg * PSTR + cl + 1]       = f2tf32(p1);
            Ps[(rg + 8) * PSTR + cl]     = f2tf32(p2);
            Ps[(rg + 8) * PSTR + cl + 1] = f2tf32(p3);
        }
        sum0 += __shfl_xor_sync(0xffffffffu, sum0, 1);
        sum0 += __shfl_xor_sync(0xffffffffu, sum0, 2);
        sum1 += __shfl_xor_sync(0xffffffffu, sum1, 1);
        sum1 += __shfl_xor_sync(0xffffffffu, sum1, 2);
        if (tg == 0) {
            psum[warpCol * 64 + rg]     = sum0;
            psum[warpCol * 64 + rg + 8] = sum1;
        }
        CP_WAIT(0);                         // V arrived (overlapped with S+softmax)
        __syncthreads();

        // stats update (one owner per row)
        if (warpCol == 0 && tg == 0) {
            lS[rg]     = lS[rg]     * resc0 + psum[rg]     + psum[64 + rg];
            lS[rg + 8] = lS[rg + 8] * resc1 + psum[rg + 8] + psum[64 + rg + 8];
            mS[rg]     = m0;
            mS[rg + 8] = m1;
        }

        // ---- O = O*resc + P V : warp tile 16 x 128 ----
#pragma unroll
        for (int nt = 0; nt < 16; nt++) {
            o[nt][0] *= resc0; o[nt][1] *= resc0;
            o[nt][2] *= resc1; o[nt][3] *= resc1;
        }
#pragma unroll
        for (int kk8 = 0; kk8 < 8; kk8++) {
            const int kk = kk8 * 8;
            uint32_t a[4];
            a[0] = Ps[rg * PSTR + kk + tg];
            a[1] = Ps[(rg + 8) * PSTR + kk + tg];
            a[2] = Ps[rg * PSTR + kk + tg + 4];
            a[3] = Ps[(rg + 8) * PSTR + kk + tg + 4];
#pragma unroll
            for (int nt = 0; nt < 16; nt++) {
                int n = warpCol * 128 + nt * 8 + g;
                uint32_t bb2[2];
                bb2[0] = Vs[(kk + tg) * VSTR + n];
                bb2[1] = Vs[(kk + tg + 4) * VSTR + n];
                mma168(o[nt], a, bb2);
            }
        }
    }
    __syncthreads();

    // epilogue: normalize + write
    float linv0 = 1.f / lS[rg];
    float linv1 = 1.f / lS[rg + 8];
    size_t ob0 = ((size_t)b * SS + (q0 + rg))     * HIDD + h * HDD;
    size_t ob1 = ((size_t)b * SS + (q0 + rg + 8)) * HIDD + h * HDD;
#pragma unroll
    for (int nt = 0; nt < 16; nt++) {
        int col = warpCol * 128 + nt * 8 + 2 * tg;
        *(float2*)&og[ob0 + col] = make_float2(o[nt][0] * linv0, o[nt][1] * linv0);
        *(float2*)&og[ob1 + col] = make_float2(o[nt][2] * linv1, o[nt][3] * linv1);
    }
}

// ---------------------------------------------------------------------------
extern "C" void kernel_launch(void* const* d_in, const int* in_sizes, int n_in,
                              void* d_out, int out_size)
{
    const float* hidden = (const float*)d_in[0];
    const float* fr     = (const float*)d_in[1];
    const float* fi     = (const float*)d_in[2];
    // d_in[3] = mask (causal handled analytically)
    const float* Wqkv   = (const float*)d_in[4];
    const float* Wo     = (const float*)d_in[5];
    float* out = (float*)d_out;

    float *qb, *kb, *vb, *ob;
    cudaGetSymbolAddress((void**)&qb, g_q);
    cudaGetSymbolAddress((void**)&kb, g_k);
    cudaGetSymbolAddress((void**)&vb, g_v);
    cudaGetSymbolAddress((void**)&ob, g_o);

    // 1) QKV + RoPE on tf32 mma.sync (pipelined)
    dim3 g1(3072 / 128, 4096 / 128);
    qkv_mma_kernel<<<g1, 256>>>(hidden, Wqkv, fr, fi);

    // 2) tensor-core flash attention (cp.async pipelined)
    const int asmB = (3 * 64 * QSTR + 64 * PSTR + 64 * 2 + 128 * 2) * 4;
    cudaFuncSetAttribute(attn_mma_kernel, cudaFuncAttributeMaxDynamicSharedMemorySize, asmB);
    dim3 g2(SS / 64, NHH, BB);
    attn_mma_kernel<<<g2, 256, asmB>>>(qb, kb, vb, ob);

    // 3) output projection on tf32 mma.sync (pipelined)
    dim3 g3(1024 / 128, 4096 / 128);
    o_mma_kernel<<<g3, 256>>>(ob, Wo, out);
}

// round 9
// speedup vs baseline: 1.2452x; 1.2452x over previous
#include <cuda_runtime.h>
#include <cstdint>

#define BB   2
#define SS   2048
#define HIDD 1024
#define NHH  4
#define HDD  256

// Scratch (allocation-free rule -> __device__ globals)
__device__ float g_q[BB*NHH*SS*HDD];
__device__ float g_k[BB*NHH*SS*HDD];
__device__ float g_v[BB*NHH*SS*HDD];
__device__ float g_o[BB*SS*HIDD];

// ---------------------------------------------------------------------------
// helpers (base PTX ISA, works on sm_103 target)
// ---------------------------------------------------------------------------
__device__ __forceinline__ void mma168(float* c, const uint32_t* a, const uint32_t* b) {
    asm volatile(
        "mma.sync.aligned.m16n8k8.row.col.f32.tf32.tf32.f32 "
        "{%0,%1,%2,%3}, {%4,%5,%6,%7}, {%8,%9}, {%0,%1,%2,%3};"
        : "+f"(c[0]), "+f"(c[1]), "+f"(c[2]), "+f"(c[3])
        : "r"(a[0]), "r"(a[1]), "r"(a[2]), "r"(a[3]), "r"(b[0]), "r"(b[1]));
}
__device__ __forceinline__ uint32_t f2tf32(float x) {
    uint32_t u;
    asm("cvt.rna.tf32.f32 %0, %1;" : "=r"(u) : "f"(x));
    return u;
}
__device__ __forceinline__ float roundtf(float x) {
    return __uint_as_float(f2tf32(x));
}

// ===========================================================================
// GEMM kernels: tf32 mma.sync, R6 mainloop (2 CTAs/SM, no prefetch).
// ===========================================================================
#define TSTR 36

__device__ __forceinline__ void mma_mainloop(
    const float* __restrict__ A, const float* __restrict__ Bmat,
    int m0, int n0, uint32_t* As, uint32_t* Bs, float c[4][4][4])
{
    const int tid  = threadIdx.x;
    const int wid  = tid >> 5, lane = tid & 31;
    const int g    = lane >> 2, tg = lane & 3;
    const int warpM = wid >> 2, warpN = wid & 3;

#pragma unroll
    for (int mt = 0; mt < 4; mt++)
#pragma unroll
        for (int nt = 0; nt < 4; nt++)
#pragma unroll
            for (int r = 0; r < 4; r++) c[mt][nt][r] = 0.f;

    for (int kt = 0; kt < 32; kt++) {
        const int k0 = kt * 32;
        __syncthreads();
        const float* Ag = A    + (size_t)m0 * 1024 + k0;
        const float* Bg = Bmat + (size_t)n0 * 1024 + k0;
#pragma unroll
        for (int j = 0; j < 4; j++) {
            int f   = tid * 4 + j;
            int row = f >> 3;
            int cw  = (f & 7) * 4;
            float4 va = *(const float4*)(Ag + (size_t)row * 1024 + cw);
            float4 vb = *(const float4*)(Bg + (size_t)row * 1024 + cw);
            uint4 ua = make_uint4(f2tf32(va.x), f2tf32(va.y), f2tf32(va.z), f2tf32(va.w));
            uint4 ub = make_uint4(f2tf32(vb.x), f2tf32(vb.y), f2tf32(vb.z), f2tf32(vb.w));
            *(uint4*)&As[row * TSTR + cw] = ua;
            *(uint4*)&Bs[row * TSTR + cw] = ub;
        }
        __syncthreads();

#pragma unroll
        for (int ks = 0; ks < 4; ks++) {
            const int kk = ks * 8;
            uint32_t a[4][4], b[4][2];
#pragma unroll
            for (int mt = 0; mt < 4; mt++) {
                int r = warpM * 64 + mt * 16 + g;
                a[mt][0] = As[r * TSTR + kk + tg];
                a[mt][1] = As[(r + 8) * TSTR + kk + tg];
                a[mt][2] = As[r * TSTR + kk + tg + 4];
                a[mt][3] = As[(r + 8) * TSTR + kk + tg + 4];
            }
#pragma unroll
            for (int nt = 0; nt < 4; nt++) {
                int n = warpN * 32 + nt * 8 + g;
                b[nt][0] = Bs[n * TSTR + kk + tg];
                b[nt][1] = Bs[n * TSTR + kk + tg + 4];
            }
#pragma unroll
            for (int mt = 0; mt < 4; mt++)
#pragma unroll
                for (int nt = 0; nt < 4; nt++)
                    mma168(c[mt][nt], a[mt], b[nt]);
        }
    }
}

__global__ __launch_bounds__(256, 2) void qkv_mma_kernel(
    const float* __restrict__ A, const float* __restrict__ W,
    const float* __restrict__ fr, const float* __restrict__ fi)
{
    __shared__ uint32_t As[128 * TSTR];
    __shared__ uint32_t Bs[128 * TSTR];
    const int tid  = threadIdx.x;
    const int wid  = tid >> 5, lane = tid & 31;
    const int g    = lane >> 2, tg = lane & 3;
    const int warpM = wid >> 2, warpN = wid & 3;
    const int m0 = blockIdx.y * 128;
    const int n0 = blockIdx.x * 128;

    float c[4][4][4];
    mma_mainloop(A, W, m0, n0, As, Bs, c);

    // Epilogue: RoPE + scatter, PRE-ROUNDED to tf32 so the attention kernel
    // can consume raw fp32 loads with no conversion and no extra error.
    const int which = n0 >> 10;
#pragma unroll
    for (int mt = 0; mt < 4; mt++) {
#pragma unroll
        for (int half = 0; half < 2; half++) {
            int m  = m0 + warpM * 64 + mt * 16 + g + half * 8;
            int bb = m >> 11;
            int ss = m & 2047;
#pragma unroll
            for (int nt = 0; nt < 4; nt++) {
                int n = n0 + warpN * 32 + nt * 8 + tg * 2;
                int h = (n >> 8) & 3;
                int d = n & 255;
                float x0 = c[mt][nt][half * 2];
                float x1 = c[mt][nt][half * 2 + 1];
                size_t oidx = (((size_t)(bb * NHH + h)) * SS + ss) * HDD + d;
                if (which == 2) {
                    *(float2*)&g_v[oidx] = make_float2(roundtf(x0), roundtf(x1));
                } else {
                    float fre = __ldg(&fr[(size_t)ss * 128 + (d >> 1)]);
                    float fim = __ldg(&fi[(size_t)ss * 128 + (d >> 1)]);
                    float o0 = x0 * fre - x1 * fim;
                    float o1 = x0 * fim + x1 * fre;
                    float* dst = (which == 0) ? g_q : g_k;
                    *(float2*)&dst[oidx] = make_float2(roundtf(o0), roundtf(o1));
                }
            }
        }
    }
}

__global__ __launch_bounds__(256, 2) void o_mma_kernel(
    const float* __restrict__ A, const float* __restrict__ W,
    float* __restrict__ C)
{
    __shared__ uint32_t As[128 * TSTR];
    __shared__ uint32_t Bs[128 * TSTR];
    const int tid  = threadIdx.x;
    const int wid  = tid >> 5, lane = tid & 31;
    const int g    = lane >> 2, tg = lane & 3;
    const int warpM = wid >> 2, warpN = wid & 3;
    const int m0 = blockIdx.y * 128;
    const int n0 = blockIdx.x * 128;

    float c[4][4][4];
    mma_mainloop(A, W, m0, n0, As, Bs, c);

#pragma unroll
    for (int mt = 0; mt < 4; mt++) {
#pragma unroll
        for (int half = 0; half < 2; half++) {
            int m = m0 + warpM * 64 + mt * 16 + g + half * 8;
#pragma unroll
            for (int nt = 0; nt < 4; nt++) {
                int n = n0 + warpN * 32 + nt * 8 + tg * 2;
                *(float2*)&C[(size_t)m * 1024 + n] =
                    make_float2(c[mt][nt][half * 2], c[mt][nt][half * 2 + 1]);
            }
        }
    }
}

// ===========================================================================
// Kernel 2: tensor-core causal flash attention (tf32 mma.sync).
// Inputs pre-rounded to tf32 -> plain float4 copies, no conversion.
// VSTR = 264 (=8 mod 32) -> PV b-fragment LDS are bank-conflict-free.
// ===========================================================================
#define QSTR 260
#define VSTR 264
#define PSTR 68

extern __shared__ uint32_t attn_sm[];

__global__ __launch_bounds__(256, 1) void attn_mma_kernel(
    const float* __restrict__ qg, const float* __restrict__ kg,
    const float* __restrict__ vg, float* __restrict__ og)
{
    uint32_t* Qs = attn_sm;                 // [64][QSTR]
    uint32_t* Ks = Qs + 64 * QSTR;          // [64][QSTR]
    uint32_t* Vs = Ks + 64 * QSTR;          // [64][VSTR]
    uint32_t* Ps = Vs + 64 * VSTR;          // [64][PSTR]
    float* mS   = (float*)(Ps + 64 * PSTR); // [64]
    float* lS   = mS + 64;                  // [64]
    float* pmax = lS + 64;                  // [2][64]
    float* psum = pmax + 128;               // [2][64]

    const int tid  = threadIdx.x;
    const int wid  = tid >> 5, lane = tid & 31;
    const int g    = lane >> 2, tg = lane & 3;
    const int warpRow = wid >> 1;
    const int warpCol = wid & 1;

    const int qt  = gridDim.x - 1 - blockIdx.x;   // heavy CTAs first
    const int q0  = qt * 64;
    const int h   = blockIdx.y;
    const int b   = blockIdx.z;
    const size_t base = ((size_t)(b * NHH + h)) * SS * HDD;
    const float scale = 0.0625f;                  // exact power of 2

    // load Q tile (scale is exact -> stays tf32)
#pragma unroll
    for (int it = 0; it < 16; it++) {
        int f   = tid + it * 256;
        int row = f >> 6;
        int c4  = (f & 63) * 4;
        float4 v = *(const float4*)&qg[base + (size_t)(q0 + row) * HDD + c4];
        float4 w = make_float4(v.x * scale, v.y * scale, v.z * scale, v.w * scale);
        *(float4*)((float*)Qs + row * QSTR + c4) = w;
    }
    if (tid < 64) { mS[tid] = -1e30f; lS[tid] = 0.f; }

    float o[16][4];
#pragma unroll
    for (int nt = 0; nt < 16; nt++)
#pragma unroll
        for (int r = 0; r < 4; r++) o[nt][r] = 0.f;

    const int rg = warpRow * 16 + g;

    const int nkb = qt + 1;
    for (int kbi = 0; kbi < nkb; kbi++) {
        const int k0 = kbi * 64;
        __syncthreads();                    // prev iter done reading Ks/Vs/Ps

        // K,V tile copy (pre-rounded -> raw float4)
#pragma unroll
        for (int it = 0; it < 16; it++) {
            int f   = tid + it * 256;
            int row = f >> 6;
            int c4  = (f & 63) * 4;
            size_t gi = base + (size_t)(k0 + row) * HDD + c4;
            *(uint4*)&Ks[row * QSTR + c4] = *(const uint4*)&kg[gi];
            *(uint4*)&Vs[row * VSTR + c4] = *(const uint4*)&vg[gi];
        }
        __syncthreads();

        // ---- S = Q K^T : warp tile 16 x 32 ----
        float s[4][4];
#pragma unroll
        for (int nt = 0; nt < 4; nt++)
#pragma unroll
            for (int r = 0; r < 4; r++) s[nt][r] = 0.f;

#pragma unroll 4
        for (int kk = 0; kk < 256; kk += 8) {
            uint32_t a[4];
            a[0] = Qs[rg * QSTR + kk + tg];
            a[1] = Qs[(rg + 8) * QSTR + kk + tg];
            a[2] = Qs[rg * QSTR + kk + tg + 4];
            a[3] = Qs[(rg + 8) * QSTR + kk + tg + 4];
#pragma unroll
            for (int nt = 0; nt < 4; nt++) {
                int n = warpCol * 32 + nt * 8 + g;
                uint32_t bb2[2];
                bb2[0] = Ks[n * QSTR + kk + tg];
                bb2[1] = Ks[n * QSTR + kk + tg + 4];
                mma168(s[nt], a, bb2);
            }
        }

        // causal mask on diagonal tile
        if (kbi == qt) {
#pragma unroll
            for (int nt = 0; nt < 4; nt++) {
#pragma unroll
                for (int r = 0; r < 4; r++) {
                    int row = q0 + rg + ((r & 2) ? 8 : 0);
                    int col = k0 + warpCol * 32 + nt * 8 + 2 * tg + (r & 1);
                    if (col > row) s[nt][r] = -1e30f;
                }
            }
        }

        // partial row max within this warp's 32 cols
        float mx0 = -1e30f, mx1 = -1e30f;
#pragma unroll
        for (int nt = 0; nt < 4; nt++) {
            mx0 = fmaxf(mx0, fmaxf(s[nt][0], s[nt][1]));
            mx1 = fmaxf(mx1, fmaxf(s[nt][2], s[nt][3]));
        }
        mx0 = fmaxf(mx0, __shfl_xor_sync(0xffffffffu, mx0, 1));
        mx0 = fmaxf(mx0, __shfl_xor_sync(0xffffffffu, mx0, 2));
        mx1 = fmaxf(mx1, __shfl_xor_sync(0xffffffffu, mx1, 1));
        mx1 = fmaxf(mx1, __shfl_xor_sync(0xffffffffu, mx1, 2));
        if (tg == 0) {
            pmax[warpCol * 64 + rg]     = mx0;
            pmax[warpCol * 64 + rg + 8] = mx1;
        }
        __syncthreads();

        float m0old = mS[rg], m1old = mS[rg + 8];
        float m0 = fmaxf(m0old, fmaxf(pmax[rg],     pmax[64 + rg]));
        float m1 = fmaxf(m1old, fmaxf(pmax[rg + 8], pmax[64 + rg + 8]));
        float resc0 = __expf(m0old - m0);
        float resc1 = __expf(m1old - m1);

        float sum0 = 0.f, sum1 = 0.f;
#pragma unroll
        for (int nt = 0; nt < 4; nt++) {
            int cl = warpCol * 32 + nt * 8 + 2 * tg;
            float p0 = __expf(s[nt][0] - m0);
            float p1 = __expf(s[nt][1] - m0);
            float p2 = __expf(s[nt][2] - m1);
            float p3 = __expf(s[nt][3] - m1);
            sum0 += p0 + p1;
            sum1 += p2 + p3;
            Ps[rg * PSTR + cl]           = f2tf32(p0);
            Ps[rg * PSTR + cl + 1]       = f2tf32(p1);
            Ps[(rg + 8) * PSTR + cl]     = f2tf32(p2);
            Ps[(rg + 8) * PSTR + cl + 1] = f2tf32(p3);
        }
        sum0 += __shfl_xor_sync(0xffffffffu, sum0, 1);
        sum0 += __shfl_xor_sync(0xffffffffu, sum0, 2);
        sum1 += __shfl_xor_sync(0xffffffffu, sum1, 1);
        sum1 += __shfl_xor_sync(0xffffffffu, sum1, 2);
        if (tg == 0) {
            psum[warpCol * 64 + rg]     = sum0;
            psum[warpCol * 64 + rg + 8] = sum1;
        }
        __syncthreads();

        // stats update (one owner per row)
        if (warpCol == 0 && tg == 0) {
            lS[rg]     = lS[rg]     * resc0 + psum[rg]     + psum[64 + rg];
            lS[rg + 8] = lS[rg + 8] * resc1 + psum[rg + 8] + psum[64 + rg + 8];
            mS[rg]     = m0;
            mS[rg + 8] = m1;
        }

        // ---- O = O*resc + P V : warp tile 16 x 128 ----
#pragma unroll
        for (int nt = 0; nt < 16; nt++) {
            o[nt][0] *= resc0; o[nt][1] *= resc0;
            o[nt][2] *= resc1; o[nt][3] *= resc1;
        }
#pragma unroll
        for (int kk8 = 0; kk8 < 8; kk8++) {
            const int kk = kk8 * 8;
            uint32_t a[4];
            a[0] = Ps[rg * PSTR + kk + tg];
            a[1] = Ps[(rg + 8) * PSTR + kk + tg];
            a[2] = Ps[rg * PSTR + kk + tg + 4];
            a[3] = Ps[(rg + 8) * PSTR + kk + tg + 4];
#pragma unroll
            for (int nt = 0; nt < 16; nt++) {
                int n = warpCol * 128 + nt * 8 + g;
                uint32_t bb2[2];
                bb2[0] = Vs[(kk + tg) * VSTR + n];
                bb2[1] = Vs[(kk + tg + 4) * VSTR + n];
                mma168(o[nt], a, bb2);
            }
        }
    }
    __syncthreads();

    // epilogue: normalize + write
    float linv0 = 1.f / lS[rg];
    float linv1 = 1.f / lS[rg + 8];
    size_t ob0 = ((size_t)b * SS + (q0 + rg))     * HIDD + h * HDD;
    size_t ob1 = ((size_t)b * SS + (q0 + rg + 8)) * HIDD + h * HDD;
#pragma unroll
    for (int nt = 0; nt < 16; nt++) {
        int col = warpCol * 128 + nt * 8 + 2 * tg;
        *(float2*)&og[ob0 + col] = make_float2(o[nt][0] * linv0, o[nt][1] * linv0);
        *(float2*)&og[ob1 + col] = make_float2(o[nt][2] * linv1, o[nt][3] * linv1);
    }
}

// ---------------------------------------------------------------------------
extern "C" void kernel_launch(void* const* d_in, const int* in_sizes, int n_in,
                              void* d_out, int out_size)
{
    const float* hidden = (const float*)d_in[0];
    const float* fr     = (const float*)d_in[1];
    const float* fi     = (const float*)d_in[2];
    // d_in[3] = mask (causal handled analytically)
    const float* Wqkv   = (const float*)d_in[4];
    const float* Wo     = (const float*)d_in[5];
    float* out = (float*)d_out;

    float *qb, *kb, *vb, *ob;
    cudaGetSymbolAddress((void**)&qb, g_q);
    cudaGetSymbolAddress((void**)&kb, g_k);
    cudaGetSymbolAddress((void**)&vb, g_v);
    cudaGetSymbolAddress((void**)&ob, g_o);

    // 1) QKV + RoPE on tf32 mma.sync (occ 2)
    dim3 g1(3072 / 128, 4096 / 128);
    qkv_mma_kernel<<<g1, 256>>>(hidden, Wqkv, fr, fi);

    // 2) tensor-core flash attention (conflict-free V, no cvt)
    const int asmB = (64 * QSTR + 64 * QSTR + 64 * VSTR + 64 * PSTR + 64 * 2 + 128 * 2) * 4;
    cudaFuncSetAttribute(attn_mma_kernel, cudaFuncAttributeMaxDynamicSharedMemorySize, asmB);
    dim3 g2(SS / 64, NHH, BB);
    attn_mma_kernel<<<g2, 256, asmB>>>(qb, kb, vb, ob);

    // 3) output projection on tf32 mma.sync (occ 2)
    dim3 g3(1024 / 128, 4096 / 128);
    o_mma_kernel<<<g3, 256>>>(ob, Wo, out);
}